// round 5
// baseline (speedup 1.0000x reference)
#include <cuda_runtime.h>

// ---------------------------------------------------------------------------
// GritMessagePassing: N=50000 nodes, E=800000 edges, HIDDEN=64, HEADS=8, ADIM=8
// Outputs: No [N,64] then conn [E,64], concatenated in d_out (float32).
// ---------------------------------------------------------------------------

constexpr int N_NODES = 50000;
constexpr int N_EDGES = 800000;
constexpr int HEADS   = 8;
constexpr float CLAMP_V = 5.0f;

// Scratch (static device globals: allocation-free rule)
__device__ float    g_qkv[(size_t)N_NODES * 192];   // [n][Q0..63 K64..127 V128..191]
__device__ float    g_score[(size_t)N_EDGES * 8];   // per-edge per-head clamped score
__device__ unsigned g_nmax[(size_t)N_NODES * 8];    // monotone-encoded float max
__device__ float    g_nsum[(size_t)N_NODES * 8];    // sum of exp per (node, head)
__device__ float    g_agg[(size_t)N_NODES * 64];    // UNNORMALIZED sum of e*V
__device__ float    g_rows[(size_t)N_NODES * 64];   // UNNORMALIZED sum of e*conn

// Monotone uint encoding of float for atomicMax
__device__ __forceinline__ unsigned fenc(float f) {
    unsigned u = __float_as_uint(f);
    return (u & 0x80000000u) ? ~u : (u | 0x80000000u);
}
__device__ __forceinline__ float fdec(unsigned u) {
    return (u & 0x80000000u) ? __uint_as_float(u & 0x7FFFFFFFu)
                             : __uint_as_float(~u);
}

__device__ __forceinline__ void red_v4(float* p, float a, float b, float c, float d) {
    asm volatile("red.global.add.v4.f32 [%0], {%1,%2,%3,%4};"
                 :: "l"(p), "f"(a), "f"(b), "f"(c), "f"(d) : "memory");
}

// Packed fp32x2 helpers (Blackwell FFMA2 — ptxas never auto-fuses, PTX-only).
// j-pairing: lanes carry (even-j, odd-j) partial sums; final result = lo + hi.
__device__ __forceinline__ void fma2(unsigned long long& acc,
                                     unsigned long long a, unsigned long long b) {
    asm("fma.rn.f32x2 %0, %1, %2, %0;" : "+l"(acc) : "l"(a), "l"(b));
}
__device__ __forceinline__ float hsum2(unsigned long long v) {
    float lo, hi;
    asm("mov.b64 {%0, %1}, %2;" : "=f"(lo), "=f"(hi) : "l"(v));
    return lo + hi;
}

// ---------------------------------------------------------------------------
__global__ void k_init() {
    int idx = blockIdx.x * blockDim.x + threadIdx.x;
    if (idx < N_NODES * 64) { g_agg[idx] = 0.f; g_rows[idx] = 0.f; }
    if (idx < N_NODES * 8)  { g_nsum[idx] = 0.f; g_nmax[idx] = 0x3F5FFFFFu; } // enc(-5.0f)
}

// QKV = x @ W^T + b via j-paired FFMA2. Weights in natural row-major shared.
__global__ __launch_bounds__(256, 2) void k_qkv(const float* __restrict__ x,
                                                const float* __restrict__ W,
                                                const float* __restrict__ bias) {
    __shared__ __align__(16) float sW[192 * 64];   // 48KB, natural layout
    __shared__ float sBias[192];
    const float4* Wg = (const float4*)W;
    for (int i = threadIdx.x; i < 192 * 16; i += 256) ((float4*)sW)[i] = Wg[i];
    if (threadIdx.x < 192) sBias[threadIdx.x] = bias[threadIdx.x];
    __syncthreads();

    int n = blockIdx.x * 256 + threadIdx.x;
    if (n >= N_NODES) return;

    // x row: 32 packed b64 (j-pairs), naturally packed from vector loads.
    unsigned long long xd[32];
    const ulonglong2* xp = (const ulonglong2*)(x + (size_t)n * 64);
#pragma unroll
    for (int j = 0; j < 16; j++) {
        ulonglong2 t = xp[j];
        xd[2 * j] = t.x; xd[2 * j + 1] = t.y;
    }

    float4* outp = (float4*)(g_qkv + (size_t)n * 192);
    for (int o = 0; o < 192; o += 4) {       // 4 acc chains cover FFMA latency
        unsigned long long a0 = 0, a1 = 0, a2 = 0, a3 = 0;
        const ulonglong2* w0 = (const ulonglong2*)(sW + (o    ) * 64);
        const ulonglong2* w1 = (const ulonglong2*)(sW + (o + 1) * 64);
        const ulonglong2* w2 = (const ulonglong2*)(sW + (o + 2) * 64);
        const ulonglong2* w3 = (const ulonglong2*)(sW + (o + 3) * 64);
#pragma unroll
        for (int jp = 0; jp < 16; jp++) {
            ulonglong2 u0 = w0[jp], u1 = w1[jp], u2 = w2[jp], u3 = w3[jp];
            fma2(a0, xd[2 * jp], u0.x); fma2(a0, xd[2 * jp + 1], u0.y);
            fma2(a1, xd[2 * jp], u1.x); fma2(a1, xd[2 * jp + 1], u1.y);
            fma2(a2, xd[2 * jp], u2.x); fma2(a2, xd[2 * jp + 1], u2.y);
            fma2(a3, xd[2 * jp], u3.x); fma2(a3, xd[2 * jp + 1], u3.y);
        }
        outp[o >> 2] = make_float4(sBias[o]     + hsum2(a0),
                                   sBias[o + 1] + hsum2(a1),
                                   sBias[o + 2] + hsum2(a2),
                                   sBias[o + 3] + hsum2(a3));
    }
}

// Per-edge: Eh projection via j-paired FFMA2 (rows o: Ew, o+64: Eb), conn
// nonlinearity (written to output), head scores, clamp, score store, atomicMax.
__global__ __launch_bounds__(256, 2) void k_edge(const float* __restrict__ cf_in,
                                                 const int* __restrict__ ei,
                                                 const float* __restrict__ EW,
                                                 const float* __restrict__ Eb,
                                                 const float* __restrict__ Aw,
                                                 float* __restrict__ out_conn) {
    __shared__ __align__(16) float sW[128 * 64];   // 32KB, natural layout
    __shared__ float sB[128];
    __shared__ float sA[64];
    const float4* Wg = (const float4*)EW;
    for (int i = threadIdx.x; i < 128 * 16; i += 256) ((float4*)sW)[i] = Wg[i];
    if (threadIdx.x < 128) sB[threadIdx.x] = Eb[threadIdx.x];
    if (threadIdx.x < 64) {
        int o = threadIdx.x;                      // o = h*8 + d
        sA[o] = Aw[(o & 7) * HEADS + (o >> 3)];   // Aw[d][h][0]
    }
    __syncthreads();

    int e = blockIdx.x * 256 + threadIdx.x;
    if (e >= N_EDGES) return;

    // Edge features: 32 packed b64 j-pairs, naturally packed.
    unsigned long long cfd[32];
    const ulonglong2* cp = (const ulonglong2*)(cf_in + (size_t)e * 64);
#pragma unroll
    for (int j = 0; j < 16; j++) {
        ulonglong2 t = cp[j];
        cfd[2 * j] = t.x; cfd[2 * j + 1] = t.y;
    }

    int dst = ei[e], src = ei[N_EDGES + e];
    const float* qrow = g_qkv + (size_t)dst * 192;       // Q
    const float* krow = g_qkv + (size_t)src * 192 + 64;  // K

    float sc[8] = {0, 0, 0, 0, 0, 0, 0, 0};
    float2* outc = (float2*)(out_conn + (size_t)e * 64);

    for (int o = 0; o < 64; o += 2) {        // 4 acc chains: (W,B) x (o,o+1)
        float q0 = __ldg(qrow + o),     k0 = __ldg(krow + o);
        float q1 = __ldg(qrow + o + 1), k1 = __ldg(krow + o + 1);

        unsigned long long aW0 = 0, aB0 = 0, aW1 = 0, aB1 = 0;
        const ulonglong2* w0 = (const ulonglong2*)(sW + (o     ) * 64);
        const ulonglong2* b0 = (const ulonglong2*)(sW + (o + 64) * 64);
        const ulonglong2* w1 = (const ulonglong2*)(sW + (o +  1) * 64);
        const ulonglong2* b1 = (const ulonglong2*)(sW + (o + 65) * 64);
#pragma unroll
        for (int jp = 0; jp < 16; jp++) {
            ulonglong2 uw0 = w0[jp], ub0 = b0[jp], uw1 = w1[jp], ub1 = b1[jp];
            fma2(aW0, cfd[2 * jp], uw0.x); fma2(aW0, cfd[2 * jp + 1], uw0.y);
            fma2(aB0, cfd[2 * jp], ub0.x); fma2(aB0, cfd[2 * jp + 1], ub0.y);
            fma2(aW1, cfd[2 * jp], uw1.x); fma2(aW1, cfd[2 * jp + 1], uw1.y);
            fma2(aB1, cfd[2 * jp], ub1.x); fma2(aB1, cfd[2 * jp + 1], ub1.y);
        }
        float vW0 = sB[o]      + hsum2(aW0);
        float vB0 = sB[o + 64] + hsum2(aB0);
        float vW1 = sB[o + 1]  + hsum2(aW1);
        float vB1 = sB[o + 65] + hsum2(aB1);

        float c10 = (q0 + k0) * vW0;
        float c11 = (q1 + k1) * vW1;
        float c20 = copysignf(sqrtf(fabsf(c10)), c10);  // sqrt_relu(x)-sqrt_relu(-x)
        float c21 = copysignf(sqrtf(fabsf(c11)), c11);
        float cv0 = fmaxf(c20 + vB0, 0.f);
        float cv1 = fmaxf(c21 + vB1, 0.f);
        outc[o >> 1] = make_float2(cv0, cv1);
        sc[o >> 3] += cv0 * sA[o] + cv1 * sA[o + 1];
    }

    unsigned* nm = g_nmax + (size_t)dst * 8;
    float4 s0, s1;
#pragma unroll
    for (int h = 0; h < 8; h++) {
        float v = fminf(fmaxf(sc[h], -CLAMP_V), CLAMP_V);
        ((float*)(h < 4 ? &s0 : &s1))[h & 3] = v;
        atomicMax(&nm[h], fenc(v));
    }
    float4* sp = (float4*)(g_score + (size_t)e * 8);
    sp[0] = s0; sp[1] = s1;
}

// Fused: e = exp(score - max[dst]); RED nsum; RED unnormalized e*V and e*conn.
// (Normalization by nsum deferred to k_out — nsum is constant per (dst, head),
// so sum(e/s * V) == sum(e*V)/s.)
__global__ __launch_bounds__(256) void k_exp_agg(const int* __restrict__ ei,
                                                 const float* __restrict__ conn) {
    int e = blockIdx.x * 256 + threadIdx.x;
    if (e >= N_EDGES) return;
    int dst = ei[e], src = ei[N_EDGES + e];

    const float4* sp = (const float4*)(g_score + (size_t)e * 8);
    float4 s0 = sp[0], s1 = sp[1];
    const unsigned* nm = g_nmax + (size_t)dst * 8;

    float ev[8];
#pragma unroll
    for (int h = 0; h < 8; h++) {
        float m = fdec(nm[h]);
        float s = (h < 4) ? ((float*)&s0)[h] : ((float*)&s1)[h & 3];
        ev[h] = expf(s - m);
    }
    float* ns = g_nsum + (size_t)dst * 8;
    red_v4(ns,     ev[0], ev[1], ev[2], ev[3]);
    red_v4(ns + 4, ev[4], ev[5], ev[6], ev[7]);

    const float4* vrow = (const float4*)(g_qkv + (size_t)src * 192 + 128);  // V
    const float4* crow = (const float4*)(conn + (size_t)e * 64);
    float* aggp = g_agg + (size_t)dst * 64;
    float* rowp = g_rows + (size_t)dst * 64;

#pragma unroll
    for (int q = 0; q < 16; q++) {
        float a = ev[q >> 1];
        float4 v = vrow[q];
        float4 c = crow[q];
        red_v4(aggp + q * 4, v.x * a, v.y * a, v.z * a, v.w * a);
        red_v4(rowp + q * 4, c.x * a, c.y * a, c.z * a, c.w * a);
    }
}

// No = (agg + rows @ Bw) / (nsum + 1e-16), per head.
__global__ __launch_bounds__(256) void k_out(const float* __restrict__ Bw,
                                             float* __restrict__ outNo) {
    int idx = blockIdx.x * 256 + threadIdx.x;
    if (idx >= N_NODES * 64) return;
    int n = idx >> 6, o = idx & 63;
    int h = o >> 3, c = o & 7;
    const float* rs = g_rows + (size_t)n * 64 + h * 8;
    float acc = g_agg[idx];
#pragma unroll
    for (int d = 0; d < 8; d++)
        acc += rs[d] * __ldg(Bw + d * 64 + h * 8 + c);  // Bw[d][h][c]
    float inv = 1.0f / (g_nsum[(size_t)n * 8 + h] + 1e-16f);
    outNo[idx] = acc * inv;
}

// ---------------------------------------------------------------------------
extern "C" void kernel_launch(void* const* d_in, const int* in_sizes, int n_in,
                              void* d_out, int out_size) {
    const float* x    = (const float*)d_in[0];
    const float* cf   = (const float*)d_in[1];
    const int*   ei   = (const int*)  d_in[2];
    const float* qkvw = (const float*)d_in[3];
    const float* qkvb = (const float*)d_in[4];
    const float* Ew   = (const float*)d_in[5];
    const float* Ebb  = (const float*)d_in[6];
    const float* Aw   = (const float*)d_in[7];
    const float* Bw   = (const float*)d_in[8];

    float* outNo   = (float*)d_out;
    float* outConn = outNo + (size_t)N_NODES * 64;

    k_init   <<<(N_NODES * 64 + 255) / 256, 256>>>();
    k_qkv    <<<(N_NODES + 255) / 256, 256>>>(x, qkvw, qkvb);
    k_edge   <<<N_EDGES / 256, 256>>>(cf, ei, Ew, Ebb, Aw, outConn);
    k_exp_agg<<<N_EDGES / 256, 256>>>(ei, outConn);
    k_out    <<<(N_NODES * 64 + 255) / 256, 256>>>(Bw, outNo);
}

// round 11
// speedup vs baseline: 1.4096x; 1.4096x over previous
#include <cuda_runtime.h>

// ---------------------------------------------------------------------------
// GritMessagePassing: N=50000 nodes, E=800000 edges, HIDDEN=64, HEADS=8, ADIM=8
// Outputs: No [N,64] then conn [E,64], concatenated in d_out (float32).
//
// Key identity: scores are clamped to [-5,5] and softmax is shift-invariant,
// so exp(s - max)/sum == exp(s - 5)/sum with all terms in [e^-10, 1].
// => no segment-max pass, no g_nmax, and the edge pipeline fuses into ONE
// kernel: projection + nonlinearity + score + exp + RED(nsum) + RED(agg).
// Normalization by nsum and the (linear) Bw matmul commute with the segment
// sum, so both fold: agg += e*V + (e*conn)@Bw, out = agg/(nsum+1e-16).
// ---------------------------------------------------------------------------

constexpr int N_NODES = 50000;
constexpr int N_EDGES = 800000;
constexpr int HEADS   = 8;
constexpr float CLAMP_V = 5.0f;

// Scratch (static device globals: allocation-free rule)
__device__ float g_qkv[(size_t)N_NODES * 192];   // [n][Q0..63 K64..127 V128..191]
__device__ float g_nsum[(size_t)N_NODES * 8];    // sum of exp(s-5) per (node, head)
__device__ float g_agg[(size_t)N_NODES * 64];    // UNNORM sum of e*V + (e*conn)@Bw

__device__ __forceinline__ void red_v4(float* p, float a, float b, float c, float d) {
    asm volatile("red.global.add.v4.f32 [%0], {%1,%2,%3,%4};"
                 :: "l"(p), "f"(a), "f"(b), "f"(c), "f"(d) : "memory");
}
__device__ __forceinline__ void red_v4f(float* p, float4 v) {
    red_v4(p, v.x, v.y, v.z, v.w);
}

// Packed fp32x2 helpers (Blackwell FFMA2 — ptxas never auto-fuses, PTX-only).
// j-pairing: lanes carry (even-j, odd-j) partial sums; final result = lo + hi.
__device__ __forceinline__ void fma2(unsigned long long& acc,
                                     unsigned long long a, unsigned long long b) {
    asm("fma.rn.f32x2 %0, %1, %2, %0;" : "+l"(acc) : "l"(a), "l"(b));
}
__device__ __forceinline__ float hsum2(unsigned long long v) {
    float lo, hi;
    asm("mov.b64 {%0, %1}, %2;" : "=f"(lo), "=f"(hi) : "l"(v));
    return lo + hi;
}

// ---------------------------------------------------------------------------
__global__ __launch_bounds__(256) void k_init() {
    int idx = blockIdx.x * blockDim.x + threadIdx.x;
    if (idx < N_NODES * 16) ((float4*)g_agg)[idx] = make_float4(0.f, 0.f, 0.f, 0.f);
    if (idx < N_NODES * 2)  ((float4*)g_nsum)[idx] = make_float4(0.f, 0.f, 0.f, 0.f);
}

// QKV = x @ W^T + b via j-paired FFMA2. Weights in natural row-major shared.
__global__ __launch_bounds__(256, 2) void k_qkv(const float* __restrict__ x,
                                                const float* __restrict__ W,
                                                const float* __restrict__ bias) {
    __shared__ __align__(16) float sW[192 * 64];   // 48KB, natural layout
    __shared__ float sBias[192];
    const float4* Wg = (const float4*)W;
    for (int i = threadIdx.x; i < 192 * 16; i += 256) ((float4*)sW)[i] = Wg[i];
    if (threadIdx.x < 192) sBias[threadIdx.x] = bias[threadIdx.x];
    __syncthreads();

    int n = blockIdx.x * 256 + threadIdx.x;
    if (n >= N_NODES) return;

    unsigned long long xd[32];
    const ulonglong2* xp = (const ulonglong2*)(x + (size_t)n * 64);
#pragma unroll
    for (int j = 0; j < 16; j++) {
        ulonglong2 t = xp[j];
        xd[2 * j] = t.x; xd[2 * j + 1] = t.y;
    }

    float4* outp = (float4*)(g_qkv + (size_t)n * 192);
    for (int o = 0; o < 192; o += 4) {       // 4 acc chains cover FFMA latency
        unsigned long long a0 = 0, a1 = 0, a2 = 0, a3 = 0;
        const ulonglong2* w0 = (const ulonglong2*)(sW + (o    ) * 64);
        const ulonglong2* w1 = (const ulonglong2*)(sW + (o + 1) * 64);
        const ulonglong2* w2 = (const ulonglong2*)(sW + (o + 2) * 64);
        const ulonglong2* w3 = (const ulonglong2*)(sW + (o + 3) * 64);
#pragma unroll
        for (int jp = 0; jp < 16; jp++) {
            ulonglong2 u0 = w0[jp], u1 = w1[jp], u2 = w2[jp], u3 = w3[jp];
            fma2(a0, xd[2 * jp], u0.x); fma2(a0, xd[2 * jp + 1], u0.y);
            fma2(a1, xd[2 * jp], u1.x); fma2(a1, xd[2 * jp + 1], u1.y);
            fma2(a2, xd[2 * jp], u2.x); fma2(a2, xd[2 * jp + 1], u2.y);
            fma2(a3, xd[2 * jp], u3.x); fma2(a3, xd[2 * jp + 1], u3.y);
        }
        outp[o >> 2] = make_float4(sBias[o]     + hsum2(a0),
                                   sBias[o + 1] + hsum2(a1),
                                   sBias[o + 2] + hsum2(a2),
                                   sBias[o + 3] + hsum2(a3));
    }
}

// FUSED edge kernel. One thread per edge. Two half passes (heads 0-3, 4-7);
// per half: hoisted Q/K gather -> FFMA2 projection -> conn (regs + output
// store) -> scores -> exp(s-5) -> RED nsum -> hoisted V gather -> Bw-folded
// RED into g_agg.
__global__ __launch_bounds__(128, 2) void k_edge_agg(const float* __restrict__ cf_in,
                                                     const int* __restrict__ ei,
                                                     const float* __restrict__ EW,
                                                     const float* __restrict__ Eb,
                                                     const float* __restrict__ Aw,
                                                     const float* __restrict__ Bw,
                                                     float* __restrict__ out_conn) {
    __shared__ __align__(16) float sW[128 * 64];   // 32KB E_weight, natural layout
    __shared__ float  sB[128];
    __shared__ float  sA[64];
    __shared__ float4 sBw[128];                    // Bw[d][h][c]: [d*16 + h*2 + c4]
    const float4* Wg = (const float4*)EW;
    for (int i = threadIdx.x; i < 128 * 16; i += 128) ((float4*)sW)[i] = Wg[i];
    sB[threadIdx.x] = Eb[threadIdx.x];
    if (threadIdx.x < 64) {
        int o = threadIdx.x;                      // o = h*8 + d
        sA[o] = Aw[(o & 7) * HEADS + (o >> 3)];   // Aw[d][h][0]
    }
    sBw[threadIdx.x] = ((const float4*)Bw)[threadIdx.x];
    __syncthreads();

    int e = blockIdx.x * 128 + threadIdx.x;
    if (e >= N_EDGES) return;

    // Edge features: 32 packed b64 j-pairs, naturally packed.
    unsigned long long cfd[32];
    const ulonglong2* cp = (const ulonglong2*)(cf_in + (size_t)e * 64);
#pragma unroll
    for (int j = 0; j < 16; j++) {
        ulonglong2 t = cp[j];
        cfd[2 * j] = t.x; cfd[2 * j + 1] = t.y;
    }

    int dst = __ldg(ei + e), src = __ldg(ei + N_EDGES + e);
    const float4* qp = (const float4*)(g_qkv + (size_t)dst * 192);        // Q
    const float4* kp = (const float4*)(g_qkv + (size_t)src * 192 + 64);   // K
    const float4* vp = (const float4*)(g_qkv + (size_t)src * 192 + 128);  // V
    float4* outc = (float4*)(out_conn + (size_t)e * 64);
    float* nsp  = g_nsum + (size_t)dst * 8;
    float* aggp = g_agg  + (size_t)dst * 64;

    for (int half = 0; half < 2; half++) {
        // Hoisted Q+K gather for this half (16 LDG.128 in flight).
        float qk[32];
#pragma unroll
        for (int j = 0; j < 8; j++) {
            float4 a = qp[half * 8 + j];
            float4 b = kp[half * 8 + j];
            qk[4 * j]     = a.x + b.x;
            qk[4 * j + 1] = a.y + b.y;
            qk[4 * j + 2] = a.z + b.z;
            qk[4 * j + 3] = a.w + b.w;
        }

        float conn32[32];
        float sc[4] = {0.f, 0.f, 0.f, 0.f};
        for (int oo = 0; oo < 32; oo += 2) {  // 4 acc chains: (W,B) x (o,o+1)
            int o = half * 32 + oo;
            unsigned long long aW0 = 0, aB0 = 0, aW1 = 0, aB1 = 0;
            const ulonglong2* w0 = (const ulonglong2*)(sW + (o     ) * 64);
            const ulonglong2* b0 = (const ulonglong2*)(sW + (o + 64) * 64);
            const ulonglong2* w1 = (const ulonglong2*)(sW + (o +  1) * 64);
            const ulonglong2* b1 = (const ulonglong2*)(sW + (o + 65) * 64);
#pragma unroll
            for (int jp = 0; jp < 16; jp++) {
                ulonglong2 uw0 = w0[jp], ub0 = b0[jp], uw1 = w1[jp], ub1 = b1[jp];
                fma2(aW0, cfd[2 * jp], uw0.x); fma2(aW0, cfd[2 * jp + 1], uw0.y);
                fma2(aB0, cfd[2 * jp], ub0.x); fma2(aB0, cfd[2 * jp + 1], ub0.y);
                fma2(aW1, cfd[2 * jp], uw1.x); fma2(aW1, cfd[2 * jp + 1], uw1.y);
                fma2(aB1, cfd[2 * jp], ub1.x); fma2(aB1, cfd[2 * jp + 1], ub1.y);
            }
            float vW0 = sB[o]      + hsum2(aW0);
            float vB0 = sB[o + 64] + hsum2(aB0);
            float vW1 = sB[o + 1]  + hsum2(aW1);
            float vB1 = sB[o + 65] + hsum2(aB1);

            float c10 = qk[oo]     * vW0;
            float c11 = qk[oo + 1] * vW1;
            float c20 = copysignf(sqrtf(fabsf(c10)), c10);  // sqrt_relu(x)-sqrt_relu(-x)
            float c21 = copysignf(sqrtf(fabsf(c11)), c11);
            float cv0 = fmaxf(c20 + vB0, 0.f);
            float cv1 = fmaxf(c21 + vB1, 0.f);
            conn32[oo] = cv0; conn32[oo + 1] = cv1;
            sc[oo >> 3] += cv0 * sA[o] + cv1 * sA[o + 1];
        }
        // Store conn output for this half (8 float4).
#pragma unroll
        for (int q = 0; q < 8; q++)
            outc[half * 8 + q] = make_float4(conn32[4 * q], conn32[4 * q + 1],
                                             conn32[4 * q + 2], conn32[4 * q + 3]);

        // exp(clamp(s) - 5): shift-invariant softmax with fixed shift.
        float ev[4];
#pragma unroll
        for (int hh = 0; hh < 4; hh++) {
            float v = fminf(fmaxf(sc[hh], -CLAMP_V), CLAMP_V);
            ev[hh] = __expf(v - CLAMP_V);
        }
        red_v4(nsp + half * 4, ev[0], ev[1], ev[2], ev[3]);

        // Hoisted V gather for this half, then Bw-folded aggregation.
        float4 vv[8];
#pragma unroll
        for (int j = 0; j < 8; j++) vv[j] = vp[half * 8 + j];

#pragma unroll
        for (int hh = 0; hh < 4; hh++) {
            int h = half * 4 + hh;
            float evh = ev[hh];
            float rc[8];
#pragma unroll
            for (int d = 0; d < 8; d++) rc[d] = conn32[hh * 8 + d] * evh;
            float4 v0 = vv[2 * hh], v1 = vv[2 * hh + 1];
            float4 y0 = make_float4(v0.x * evh, v0.y * evh, v0.z * evh, v0.w * evh);
            float4 y1 = make_float4(v1.x * evh, v1.y * evh, v1.z * evh, v1.w * evh);
#pragma unroll
            for (int d = 0; d < 8; d++) {
                float4 w0 = sBw[d * 16 + h * 2];
                float4 w1 = sBw[d * 16 + h * 2 + 1];
                y0.x += rc[d] * w0.x; y0.y += rc[d] * w0.y;
                y0.z += rc[d] * w0.z; y0.w += rc[d] * w0.w;
                y1.x += rc[d] * w1.x; y1.y += rc[d] * w1.y;
                y1.z += rc[d] * w1.z; y1.w += rc[d] * w1.w;
            }
            red_v4f(aggp + h * 8,     y0);
            red_v4f(aggp + h * 8 + 4, y1);
        }
    }
}

// No = agg / (nsum + 1e-16), per head.
__global__ __launch_bounds__(256) void k_out(float* __restrict__ outNo) {
    int idx = blockIdx.x * 256 + threadIdx.x;
    if (idx >= N_NODES * 64) return;
    int n = idx >> 6, h = (idx & 63) >> 3;
    float inv = __frcp_rn(g_nsum[(size_t)n * 8 + h] + 1e-16f);
    outNo[idx] = g_agg[idx] * inv;
}

// ---------------------------------------------------------------------------
extern "C" void kernel_launch(void* const* d_in, const int* in_sizes, int n_in,
                              void* d_out, int out_size) {
    const float* x    = (const float*)d_in[0];
    const float* cf   = (const float*)d_in[1];
    const int*   ei   = (const int*)  d_in[2];
    const float* qkvw = (const float*)d_in[3];
    const float* qkvb = (const float*)d_in[4];
    const float* Ew   = (const float*)d_in[5];
    const float* Ebb  = (const float*)d_in[6];
    const float* Aw   = (const float*)d_in[7];
    const float* Bw   = (const float*)d_in[8];

    float* outNo   = (float*)d_out;
    float* outConn = outNo + (size_t)N_NODES * 64;

    k_init    <<<(N_NODES * 16 + 255) / 256, 256>>>();
    k_qkv     <<<(N_NODES + 255) / 256, 256>>>(x, qkvw, qkvb);
    k_edge_agg<<<N_EDGES / 128, 128>>>(cf, ei, Ew, Ebb, Aw, Bw, outConn);
    k_out     <<<(N_NODES * 64 + 255) / 256, 256>>>(outNo);
}